// round 6
// baseline (speedup 1.0000x reference)
#include <cuda_runtime.h>
#include <cuda_fp16.h>
#include <math.h>
#include <stdint.h>

#define EMB 64
#define HID 128
#define NN  50000
#define NE  800000
#define NQ  64
#define NTILES (NE / 128)

// ---------------- scratch (static device globals; no allocation) ----------------
__device__ float   g_Aq[NQ * EMB];       // (qe@Wq+bq) @ W1a
__device__ float   g_biasAB[EMB];        // b1 + be@W1b + br@W1c
__device__ float   g_biasC [EMB];        // be@W1d
__device__ float   g_ABn[NN * EMB];      // per-node: ne@Mb + biasAB + Aq[batch[n]]
__device__ float   g_Cn [NN * EMB];      // per-node: ne@Md + biasC
__device__ __half2 g_Mt    [EMB * 32];   // (Wr@W1c) transposed [n][kpair], permuted fp16
__device__ __half2 g_MbMdt [2 * EMB * 32]; // rows 0..63: We@W1b ; rows 64..127: We@W1d
__device__ __half2 g_W2t   [HID * 32];   // W2 transposed [n][kpair], permuted fp16

// ---------------- helpers ----------------
__device__ __forceinline__ void mma_f16(float& c0, float& c1, float& c2, float& c3,
                                        uint32_t a0, uint32_t a1, uint32_t a2, uint32_t a3,
                                        uint32_t b0, uint32_t b1) {
    asm volatile("mma.sync.aligned.m16n8k16.row.col.f32.f16.f16.f32 "
                 "{%0,%1,%2,%3}, {%4,%5,%6,%7}, {%8,%9}, {%0,%1,%2,%3};\n"
                 : "+f"(c0), "+f"(c1), "+f"(c2), "+f"(c3)
                 : "r"(a0), "r"(a1), "r"(a2), "r"(a3), "r"(b0), "r"(b1));
}
// permuted position of k-pair j: within each chunk of 8 pairs, order [0,4,1,5,2,6,3,7]
__device__ __forceinline__ int permp(int j) {
    int c = j >> 3, p = j & 7;
    return (c << 3) | ((p & 3) << 1) | (p >> 2);
}

// ---------------- fused prep kernel: 5 independent blocks ----------------
__global__ void prep_kernel(const float* __restrict__ qe,
                            const float* __restrict__ Wq, const float* __restrict__ bq,
                            const float* __restrict__ We, const float* __restrict__ be,
                            const float* __restrict__ Wr, const float* __restrict__ br,
                            const float* __restrict__ W1, const float* __restrict__ b1,
                            const float* __restrict__ W2) {
    __shared__ float sP[EMB * EMB];
    __shared__ float sbq[EMB];
    int b = blockIdx.x, t = threadIdx.x;

    if (b == 0) {
        // T = Wq @ W1a ; biasq = bq @ W1a ; Aq = qe @ T + biasq
        #pragma unroll
        for (int j = 0; j < 16; j++) {
            int idx = t + 256 * j;
            int k = idx >> 6, n = idx & 63;
            float s = 0.f;
            #pragma unroll 8
            for (int i = 0; i < EMB; i++) s += Wq[k * EMB + i] * W1[i * EMB + n];
            sP[idx] = s;
        }
        if (t < 64) {
            float s = 0.f;
            #pragma unroll 8
            for (int i = 0; i < EMB; i++) s += bq[i] * W1[i * EMB + t];
            sbq[t] = s;
        }
        __syncthreads();
        #pragma unroll
        for (int j = 0; j < 16; j++) {
            int idx = t + 256 * j;
            int q = idx >> 6, n = idx & 63;
            float s = sbq[n];
            #pragma unroll 8
            for (int i = 0; i < EMB; i++) s += qe[q * EMB + i] * sP[i * EMB + n];
            g_Aq[idx] = s;
        }
    } else if (b <= 3) {
        // P = X @ W1_block -> fp16 transposed+permuted into dst
        const float* X = (b == 1) ? Wr : We;
        int yoff = (b == 1) ? 128 : ((b == 2) ? 64 : 192);
        __half2* dst = (b == 1) ? g_Mt : (g_MbMdt + ((b == 2) ? 0 : EMB) * 32);
        #pragma unroll
        for (int j = 0; j < 16; j++) {
            int idx = t + 256 * j;
            int k = idx >> 6, n = idx & 63;
            float s = 0.f;
            #pragma unroll 8
            for (int i = 0; i < EMB; i++) s += X[k * EMB + i] * W1[(yoff + i) * EMB + n];
            sP[idx] = s;
        }
        __syncthreads();
        #pragma unroll
        for (int j = 0; j < 8; j++) {
            int o = t + 256 * j;                 // 2048 half2
            int n = o >> 5, pos = o & 31;
            int c = pos >> 3, q = pos & 7;
            int p = (q >> 1) + ((q & 1) << 2);
            int k0 = (c << 4) + (p << 1);
            dst[o] = __floats2half2_rn(sP[k0 * EMB + n], sP[(k0 + 1) * EMB + n]);
        }
        if (b == 2 && t < 64) {
            float s = b1[t];
            #pragma unroll 8
            for (int i = 0; i < EMB; i++)
                s += be[i] * W1[(64 + i) * EMB + t] + br[i] * W1[(128 + i) * EMB + t];
            g_biasAB[t] = s;
        }
        if (b == 3 && t < 64) {
            float s = 0.f;
            #pragma unroll 8
            for (int i = 0; i < EMB; i++) s += be[i] * W1[(192 + i) * EMB + t];
            g_biasC[t] = s;
        }
    } else {
        // W2 transpose -> fp16 permuted (4096 half2)
        #pragma unroll
        for (int j = 0; j < 16; j++) {
            int o = t + 256 * j;
            int n = o >> 5, pos = o & 31;
            int c = pos >> 3, q = pos & 7;
            int p = (q >> 1) + ((q & 1) << 2);
            int k0 = (c << 4) + (p << 1);
            g_W2t[o] = __floats2half2_rn(W2[k0 * HID + n], W2[(k0 + 1) * HID + n]);
        }
    }
}

// ---------------- node kernel: fp16 mma, [128 x 64] @ [64 x 128] ----------------
__global__ __launch_bounds__(256) void node_mma_kernel(const float* __restrict__ nodeEmb,
                                                       const int*   __restrict__ nodeBatch) {
    __shared__ __half2 sNE[128 * 40];
    __shared__ __half2 sW [128 * 40];

    int t = threadIdx.x;
    int n0 = blockIdx.x * 128;

    for (int i = t; i < 4096; i += 256) sW[(i >> 5) * 40 + (i & 31)] = g_MbMdt[i];
    #pragma unroll
    for (int j = 0; j < 8; j++) {
        int i = t + 256 * j;
        int r = i >> 4, q = i & 15;
        int n = n0 + r;
        float4 v = (n < NN) ? ((const float4*)nodeEmb)[(size_t)n * 16 + q]
                            : make_float4(0.f, 0.f, 0.f, 0.f);
        __half2* row = &sNE[r * 40];
        row[permp(2 * q)]     = __floats2half2_rn(v.x, v.y);
        row[permp(2 * q + 1)] = __floats2half2_rn(v.z, v.w);
    }
    __syncthreads();

    int w = t >> 5, lane = t & 31;
    int g = lane >> 2, tig = lane & 3;
    int rA = w * 16 + g;
    int tig2 = tig << 1;

    float acc[64];
    #pragma unroll
    for (int j = 0; j < 64; j++) acc[j] = 0.f;

    const __half2* eeLo = &sNE[rA * 40 + tig2];
    const __half2* eeHi = &sNE[(rA + 8) * 40 + tig2];
    #pragma unroll
    for (int kt = 0; kt < 4; kt++) {
        int base = kt * 8;
        uint2 va = *(const uint2*)(eeLo + base);
        uint2 vb = *(const uint2*)(eeHi + base);
        #pragma unroll
        for (int nt = 0; nt < 16; nt++) {
            uint2 wb = *(const uint2*)(&sW[(nt * 8 + g) * 40 + base + tig2]);
            mma_f16(acc[nt*4], acc[nt*4+1], acc[nt*4+2], acc[nt*4+3],
                    va.x, vb.x, va.y, vb.y, wb.x, wb.y);
        }
    }

    int nlo = n0 + rA, nhi = n0 + rA + 8;
    int qlo = (nlo < NN) ? nodeBatch[nlo] : 0;
    int qhi = (nhi < NN) ? nodeBatch[nhi] : 0;
    #pragma unroll
    for (int nt = 0; nt < 16; nt++) {
        int c = nt * 8 + tig2;
        if (nt < 8) {
            float bA0 = g_biasAB[c], bA1 = g_biasAB[c + 1];
            if (nlo < NN) {
                g_ABn[(size_t)nlo * 64 + c]     = acc[nt*4+0] + bA0 + g_Aq[qlo * 64 + c];
                g_ABn[(size_t)nlo * 64 + c + 1] = acc[nt*4+1] + bA1 + g_Aq[qlo * 64 + c + 1];
            }
            if (nhi < NN) {
                g_ABn[(size_t)nhi * 64 + c]     = acc[nt*4+2] + bA0 + g_Aq[qhi * 64 + c];
                g_ABn[(size_t)nhi * 64 + c + 1] = acc[nt*4+3] + bA1 + g_Aq[qhi * 64 + c + 1];
            }
        } else {
            int cc = c - 64;
            float bC0 = g_biasC[cc], bC1 = g_biasC[cc + 1];
            if (nlo < NN) {
                g_Cn[(size_t)nlo * 64 + cc]     = acc[nt*4+0] + bC0;
                g_Cn[(size_t)nlo * 64 + cc + 1] = acc[nt*4+1] + bC1;
            }
            if (nhi < NN) {
                g_Cn[(size_t)nhi * 64 + cc]     = acc[nt*4+2] + bC0;
                g_Cn[(size_t)nhi * 64 + cc + 1] = acc[nt*4+3] + bC1;
            }
        }
    }
}

// ---------------- persistent edge kernel: fp16 mma, 128 edges/tile ----------------
// smem (half2 units): sEE[128*40]=5120 | sMt[64*40]=2560 | sW2t[128*40]=5120
// then floats: sWh[128] | sb2[128] | int sHT[256]
#define H2_EE 0
#define H2_M  5120
#define H2_W2 7680
#define H2_END 12800
#define SME_BYTES (H2_END * 4 + (256 + 256) * 4)
#define EDGE_GRID 444

__global__ __launch_bounds__(256, 3) void edge_kernel(const float* __restrict__ edgeEmb,
                                                      const int*   __restrict__ edgeIndex,
                                                      const float* __restrict__ b2,
                                                      const float* __restrict__ Wh,
                                                      const float* __restrict__ bh,
                                                      float* __restrict__ out) {
    extern __shared__ __half2 smh[];
    __half2* sEE  = smh + H2_EE;
    __half2* sMt  = smh + H2_M;
    __half2* sW2t = smh + H2_W2;
    float*   fend = (float*)(smh + H2_END);
    float*   sWh  = fend;
    float*   sb2  = fend + 128;
    int*     sHT  = (int*)(fend + 256);

    int t = threadIdx.x;

    // ---- load weights ONCE ----
    for (int i = t; i < 2048; i += 256) sMt [(i >> 5) * 40 + (i & 31)] = g_Mt[i];
    for (int i = t; i < 4096; i += 256) sW2t[(i >> 5) * 40 + (i & 31)] = g_W2t[i];
    if (t < 128) { sWh[t] = Wh[t]; sb2[t] = b2[t]; }
    float bhv = bh[0];

    int w = t >> 5, lane = t & 31;
    int g = lane >> 2, tig = lane & 3;
    int rA = w * 16 + g;
    int tig2 = tig << 1;

    // fill positions for this thread's 8 float4 chunks
    int fpos1[8], fpos2[8], frow[8];
    #pragma unroll
    for (int j = 0; j < 8; j++) {
        int i = t + 256 * j;
        frow[j]  = i >> 4;
        int q    = i & 15;
        fpos1[j] = permp(2 * q);
        fpos2[j] = permp(2 * q + 1);
    }

    // ---- prefetch first tile ----
    float4 pvA[4], pvB[4];
    int ih = 0, itl = 0;
    int tile = blockIdx.x;
    if (tile < NTILES) {
        int e0 = tile * 128;
        #pragma unroll
        for (int j = 0; j < 4; j++) {
            int i = t + 256 * j;
            pvA[j] = ((const float4*)edgeEmb)[(size_t)(e0 + (i >> 4)) * 16 + (i & 15)];
        }
        #pragma unroll
        for (int j = 0; j < 4; j++) {
            int i = t + 256 * (j + 4);
            pvB[j] = ((const float4*)edgeEmb)[(size_t)(e0 + (i >> 4)) * 16 + (i & 15)];
        }
        if (t < 128) { ih = edgeIndex[e0 + t]; itl = edgeIndex[NE + e0 + t]; }
    }

    for (; tile < NTILES; tile += gridDim.x) {
        int e0 = tile * 128;
        __syncthreads();                 // prior tile's smem reads done
        #pragma unroll
        for (int j = 0; j < 4; j++) {
            __half2* row = &sEE[frow[j] * 40];
            row[fpos1[j]] = __floats2half2_rn(pvA[j].x, pvA[j].y);
            row[fpos2[j]] = __floats2half2_rn(pvA[j].z, pvA[j].w);
        }
        #pragma unroll
        for (int j = 0; j < 4; j++) {
            __half2* row = &sEE[frow[j + 4] * 40];
            row[fpos1[j + 4]] = __floats2half2_rn(pvB[j].x, pvB[j].y);
            row[fpos2[j + 4]] = __floats2half2_rn(pvB[j].z, pvB[j].w);
        }
        if (t < 128) { sHT[t] = ih; sHT[128 + t] = itl; }
        __syncthreads();                 // tile visible

        int nxt = tile + gridDim.x;
        bool have_n = (nxt < NTILES);
        int e0n = nxt * 128;

        // ---- gather G = ABn[head] + Cn[tail] directly into accumulators (L2) ----
        int h0 = sHT[rA],     t0 = sHT[128 + rA];
        int h1 = sHT[rA + 8], t1 = sHT[128 + rA + 8];
        const float2* A0 = (const float2*)(g_ABn + (size_t)h0 * EMB);
        const float2* C0 = (const float2*)(g_Cn  + (size_t)t0 * EMB);
        const float2* A1 = (const float2*)(g_ABn + (size_t)h1 * EMB);
        const float2* C1 = (const float2*)(g_Cn  + (size_t)t1 * EMB);

        float acc[32];
        #pragma unroll
        for (int nt = 0; nt < 8; nt++) {
            float2 a = A0[nt * 4 + tig], c = C0[nt * 4 + tig];
            float2 b = A1[nt * 4 + tig], d = C1[nt * 4 + tig];
            acc[nt*4+0] = a.x + c.x; acc[nt*4+1] = a.y + c.y;
            acc[nt*4+2] = b.x + d.x; acc[nt*4+3] = b.y + d.y;
        }

        // ---- stage 1: H = relu(EE @ M + G) ----
        const __half2* eeLo = &sEE[rA * 40 + tig2];
        const __half2* eeHi = &sEE[(rA + 8) * 40 + tig2];
        #pragma unroll
        for (int kt = 0; kt < 4; kt++) {
            int base = kt * 8;
            uint2 va = *(const uint2*)(eeLo + base);
            uint2 vb = *(const uint2*)(eeHi + base);
            #pragma unroll
            for (int nt = 0; nt < 8; nt++) {
                uint2 wb = *(const uint2*)(&sMt[(nt * 8 + g) * 40 + base + tig2]);
                mma_f16(acc[nt*4], acc[nt*4+1], acc[nt*4+2], acc[nt*4+3],
                        va.x, vb.x, va.y, vb.y, wb.x, wb.y);
            }
        }

        // ---- prefetch next tile, part A + indices (hidden under pack + stage 2) ----
        if (have_n) {
            #pragma unroll
            for (int j = 0; j < 4; j++) {
                int i = t + 256 * j;
                pvA[j] = ((const float4*)edgeEmb)[(size_t)(e0n + (i >> 4)) * 16 + (i & 15)];
            }
            if (t < 128) { ih = edgeIndex[e0n + t]; itl = edgeIndex[NE + e0n + t]; }
        }

        __syncwarp();
        #pragma unroll
        for (int nt = 0; nt < 8; nt++) {
            int pos = permp(nt * 4 + tig);
            sEE[rA * 40 + pos]       = __floats2half2_rn(fmaxf(acc[nt*4+0], 0.f),
                                                         fmaxf(acc[nt*4+1], 0.f));
            sEE[(rA + 8) * 40 + pos] = __floats2half2_rn(fmaxf(acc[nt*4+2], 0.f),
                                                         fmaxf(acc[nt*4+3], 0.f));
        }
        __syncwarp();

        // ---- stage 2, half 0 (cols 0..63) ----
        float p0 = 0.f, p1 = 0.f;
        {
            float acc2[32];
            #pragma unroll
            for (int nt = 0; nt < 8; nt++) {
                float bz0 = sb2[nt * 8 + tig2];
                float bz1 = sb2[nt * 8 + tig2 + 1];
                acc2[nt*4+0] = bz0; acc2[nt*4+1] = bz1;
                acc2[nt*4+2] = bz0; acc2[nt*4+3] = bz1;
            }
            #pragma unroll
            for (int kt = 0; kt < 4; kt++) {
                int base = kt * 8;
                uint2 va = *(const uint2*)(eeLo + base);
                uint2 vb = *(const uint2*)(eeHi + base);
                #pragma unroll
                for (int nt = 0; nt < 8; nt++) {
                    uint2 wb = *(const uint2*)(&sW2t[(nt * 8 + g) * 40 + base + tig2]);
                    mma_f16(acc2[nt*4], acc2[nt*4+1], acc2[nt*4+2], acc2[nt*4+3],
                            va.x, vb.x, va.y, vb.y, wb.x, wb.y);
                }
            }
            #pragma unroll
            for (int nt = 0; nt < 8; nt++) {
                float w0 = sWh[nt * 8 + tig2];
                float w1 = sWh[nt * 8 + tig2 + 1];
                p0 += fmaxf(acc2[nt*4+0], 0.f) * w0 + fmaxf(acc2[nt*4+1], 0.f) * w1;
                p1 += fmaxf(acc2[nt*4+2], 0.f) * w0 + fmaxf(acc2[nt*4+3], 0.f) * w1;
            }
        }

        // ---- prefetch next tile, part B ----
        if (have_n) {
            #pragma unroll
            for (int j = 0; j < 4; j++) {
                int i = t + 256 * (j + 4);
                pvB[j] = ((const float4*)edgeEmb)[(size_t)(e0n + (i >> 4)) * 16 + (i & 15)];
            }
        }

        // ---- stage 2, half 1 (cols 64..127) ----
        {
            float acc2[32];
            #pragma unroll
            for (int nt = 0; nt < 8; nt++) {
                float bz0 = sb2[64 + nt * 8 + tig2];
                float bz1 = sb2[64 + nt * 8 + tig2 + 1];
                acc2[nt*4+0] = bz0; acc2[nt*4+1] = bz1;
                acc2[nt*4+2] = bz0; acc2[nt*4+3] = bz1;
            }
            #pragma unroll
            for (int kt = 0; kt < 4; kt++) {
                int base = kt * 8;
                uint2 va = *(const uint2*)(eeLo + base);
                uint2 vb = *(const uint2*)(eeHi + base);
                #pragma unroll
                for (int nt = 0; nt < 8; nt++) {
                    uint2 wb = *(const uint2*)(&sW2t[(64 + nt * 8 + g) * 40 + base + tig2]);
                    mma_f16(acc2[nt*4], acc2[nt*4+1], acc2[nt*4+2], acc2[nt*4+3],
                            va.x, vb.x, va.y, vb.y, wb.x, wb.y);
                }
            }
            #pragma unroll
            for (int nt = 0; nt < 8; nt++) {
                float w0 = sWh[64 + nt * 8 + tig2];
                float w1 = sWh[64 + nt * 8 + tig2 + 1];
                p0 += fmaxf(acc2[nt*4+0], 0.f) * w0 + fmaxf(acc2[nt*4+1], 0.f) * w1;
                p1 += fmaxf(acc2[nt*4+2], 0.f) * w0 + fmaxf(acc2[nt*4+3], 0.f) * w1;
            }
        }

        p0 += __shfl_xor_sync(0xffffffffu, p0, 1);
        p0 += __shfl_xor_sync(0xffffffffu, p0, 2);
        p1 += __shfl_xor_sync(0xffffffffu, p1, 1);
        p1 += __shfl_xor_sync(0xffffffffu, p1, 2);
        if (tig == 0) {
            out[e0 + rA]     = 1.f / (1.f + __expf(-(p0 + bhv)));
            out[e0 + rA + 8] = 1.f / (1.f + __expf(-(p1 + bhv)));
        }
    }
}

// ---------------- launch ----------------
extern "C" void kernel_launch(void* const* d_in, const int* in_sizes, int n_in,
                              void* d_out, int out_size) {
    const float* question_emb = (const float*)d_in[0];
    const float* node_emb     = (const float*)d_in[1];
    const float* edge_emb     = (const float*)d_in[2];
    const int*   edge_index   = (const int*)  d_in[3];
    const int*   node_batch   = (const int*)  d_in[4];
    const float* Wq = (const float*)d_in[5];
    const float* bq = (const float*)d_in[6];
    const float* We = (const float*)d_in[7];
    const float* be = (const float*)d_in[8];
    const float* Wr = (const float*)d_in[9];
    const float* br = (const float*)d_in[10];
    const float* W1 = (const float*)d_in[11];
    const float* b1 = (const float*)d_in[12];
    const float* W2 = (const float*)d_in[13];
    const float* b2 = (const float*)d_in[14];
    const float* Wh = (const float*)d_in[15];
    const float* bh = (const float*)d_in[16];
    float* out = (float*)d_out;

    prep_kernel<<<5, 256>>>(question_emb, Wq, bq, We, be, Wr, br, W1, b1, W2);
    node_mma_kernel<<<(NN + 127) / 128, 256>>>(node_emb, node_batch);

    cudaFuncSetAttribute(edge_kernel, cudaFuncAttributeMaxDynamicSharedMemorySize, SME_BYTES);
    edge_kernel<<<EDGE_GRID, 256, SME_BYTES>>>(edge_emb, edge_index, b2, Wh, bh, out);
}

// round 7
// speedup vs baseline: 1.4058x; 1.4058x over previous
#include <cuda_runtime.h>
#include <cuda_fp16.h>
#include <math.h>
#include <stdint.h>

#define EMB 64
#define HID 128
#define NN  50000
#define NE  800000
#define NQ  64
#define NTILES (NE / 128)

// ---------------- scratch (static device globals; no allocation) ----------------
__device__ float   g_qr[NQ * EMB];        // q_repr = qe@Wq + bq
__device__ float   g_Aq[NQ * EMB];        // q_repr @ W1a
__device__ float   g_M [EMB * EMB];       // Wr @ W1c
__device__ float   g_Mb[EMB * EMB];       // We @ W1b
__device__ float   g_Md[EMB * EMB];       // We @ W1d
__device__ float   g_biasAB[EMB];         // b1 + be@W1b + br@W1c
__device__ float   g_biasC [EMB];         // be@W1d
__device__ float   g_ABn[NN * EMB];       // per-node: ne@Mb + biasAB + Aq[batch[n]]
__device__ float   g_Cn [NN * EMB];       // per-node: ne@Md + biasC
__device__ __half2 g_Mt    [EMB * 32];    // M transposed [n][kpair], permuted fp16
__device__ __half2 g_MbMdt [2 * EMB * 32];// rows 0..63: Mb ; rows 64..127: Md
__device__ __half2 g_W2t   [HID * 32];    // W2 transposed [n][kpair], permuted fp16

// ---------------- helpers ----------------
__device__ __forceinline__ void mma_f16(float& c0, float& c1, float& c2, float& c3,
                                        uint32_t a0, uint32_t a1, uint32_t a2, uint32_t a3,
                                        uint32_t b0, uint32_t b1) {
    asm volatile("mma.sync.aligned.m16n8k16.row.col.f32.f16.f16.f32 "
                 "{%0,%1,%2,%3}, {%4,%5,%6,%7}, {%8,%9}, {%0,%1,%2,%3};\n"
                 : "+f"(c0), "+f"(c1), "+f"(c2), "+f"(c3)
                 : "r"(a0), "r"(a1), "r"(a2), "r"(a3), "r"(b0), "r"(b1));
}
// permuted position of k-pair j: within each chunk of 8 pairs, order [0,4,1,5,2,6,3,7]
__device__ __forceinline__ int permp(int j) {
    int c = j >> 3, p = j & 7;
    return (c << 3) | ((p & 3) << 1) | (p >> 2);
}

// ---------------- prep 0: q_repr ----------------
__global__ void prep0_kernel(const float* __restrict__ qe,
                             const float* __restrict__ Wq,
                             const float* __restrict__ bq) {
    int idx = blockIdx.x * 256 + threadIdx.x;
    int q = idx >> 6, j = idx & 63;
    float s = bq[j];
    #pragma unroll 8
    for (int i = 0; i < EMB; i++) s += qe[q * EMB + i] * Wq[i * EMB + j];
    g_qr[idx] = s;
}

// ---------------- prep 1: folded matrices + biases (fp32) ----------------
__global__ void prep1_kernel(const float* __restrict__ We,
                             const float* __restrict__ be,
                             const float* __restrict__ Wr,
                             const float* __restrict__ br,
                             const float* __restrict__ W1,
                             const float* __restrict__ b1) {
    int b = blockIdx.x;
    if (b < 64) {
        int m   = b >> 4;
        int idx = (b & 15) * 256 + threadIdx.x;
        int k = idx >> 6, j = idx & 63;
        float s = 0.f;
        if (m == 0) {
            #pragma unroll 8
            for (int i = 0; i < EMB; i++) s += g_qr[k * EMB + i] * W1[i * EMB + j];
            g_Aq[idx] = s;
        } else if (m == 1) {
            #pragma unroll 8
            for (int i = 0; i < EMB; i++) s += Wr[k * EMB + i] * W1[(128 + i) * EMB + j];
            g_M[idx] = s;
        } else if (m == 2) {
            #pragma unroll 8
            for (int i = 0; i < EMB; i++) s += We[k * EMB + i] * W1[(64 + i) * EMB + j];
            g_Mb[idx] = s;
        } else {
            #pragma unroll 8
            for (int i = 0; i < EMB; i++) s += We[k * EMB + i] * W1[(192 + i) * EMB + j];
            g_Md[idx] = s;
        }
    } else {
        if (threadIdx.x < EMB) {
            int j = threadIdx.x;
            float sAB = b1[j], sC = 0.f;
            #pragma unroll 8
            for (int i = 0; i < EMB; i++) {
                sAB += be[i] * W1[(64 + i) * EMB + j] + br[i] * W1[(128 + i) * EMB + j];
                sC  += be[i] * W1[(192 + i) * EMB + j];
            }
            g_biasAB[j] = sAB;
            g_biasC[j]  = sC;
        }
    }
}

// ---------------- prep 2: transpose+permute weights to fp16 B-fragment layout ----------------
__global__ void prep2_kernel(const float* __restrict__ W2) {
    int idx = blockIdx.x * 256 + threadIdx.x;   // 40 blocks -> 10240
    if (idx < 2048) {            // g_Mt: 64 n-rows x 32 kpairs
        int n = idx >> 5, pos = idx & 31;
        int c = pos >> 3, q = pos & 7;
        int p = (q >> 1) + ((q & 1) << 2);
        int k0 = (c << 4) + (p << 1);
        g_Mt[idx] = __floats2half2_rn(g_M[k0 * EMB + n], g_M[(k0 + 1) * EMB + n]);
    } else if (idx < 6144) {     // g_W2t: 128 n-rows x 32 kpairs
        int i2 = idx - 2048;
        int n = i2 >> 5, pos = i2 & 31;
        int c = pos >> 3, q = pos & 7;
        int p = (q >> 1) + ((q & 1) << 2);
        int k0 = (c << 4) + (p << 1);
        g_W2t[i2] = __floats2half2_rn(W2[k0 * HID + n], W2[(k0 + 1) * HID + n]);
    } else {                     // g_MbMdt: 128 n-rows (0..63 Mb, 64..127 Md) x 32 kpairs
        int i2 = idx - 6144;
        int n = i2 >> 5, pos = i2 & 31;
        int c = pos >> 3, q = pos & 7;
        int p = (q >> 1) + ((q & 1) << 2);
        int k0 = (c << 4) + (p << 1);
        const float* src = (n < 64) ? g_Mb : g_Md;
        int nn = n & 63;
        g_MbMdt[i2] = __floats2half2_rn(src[k0 * EMB + nn], src[(k0 + 1) * EMB + nn]);
    }
}

// ---------------- node kernel: fp16 mma, [128 x 64] @ [64 x 128] ----------------
__global__ __launch_bounds__(256) void node_mma_kernel(const float* __restrict__ nodeEmb,
                                                       const int*   __restrict__ nodeBatch) {
    __shared__ __half2 sNE[128 * 40];
    __shared__ __half2 sW [128 * 40];

    int t = threadIdx.x;
    int n0 = blockIdx.x * 128;

    for (int i = t; i < 4096; i += 256) sW[(i >> 5) * 40 + (i & 31)] = g_MbMdt[i];
    #pragma unroll
    for (int j = 0; j < 8; j++) {
        int i = t + 256 * j;
        int r = i >> 4, q = i & 15;
        int n = n0 + r;
        float4 v = (n < NN) ? ((const float4*)nodeEmb)[(size_t)n * 16 + q]
                            : make_float4(0.f, 0.f, 0.f, 0.f);
        __half2* row = &sNE[r * 40];
        row[permp(2 * q)]     = __floats2half2_rn(v.x, v.y);
        row[permp(2 * q + 1)] = __floats2half2_rn(v.z, v.w);
    }
    __syncthreads();

    int w = t >> 5, lane = t & 31;
    int g = lane >> 2, tig = lane & 3;
    int rA = w * 16 + g;
    int tig2 = tig << 1;

    float acc[64];
    #pragma unroll
    for (int j = 0; j < 64; j++) acc[j] = 0.f;

    const __half2* eeLo = &sNE[rA * 40 + tig2];
    const __half2* eeHi = &sNE[(rA + 8) * 40 + tig2];
    #pragma unroll
    for (int kt = 0; kt < 4; kt++) {
        int base = kt * 8;
        uint2 va = *(const uint2*)(eeLo + base);
        uint2 vb = *(const uint2*)(eeHi + base);
        #pragma unroll
        for (int nt = 0; nt < 16; nt++) {
            uint2 wb = *(const uint2*)(&sW[(nt * 8 + g) * 40 + base + tig2]);
            mma_f16(acc[nt*4], acc[nt*4+1], acc[nt*4+2], acc[nt*4+3],
                    va.x, vb.x, va.y, vb.y, wb.x, wb.y);
        }
    }

    int nlo = n0 + rA, nhi = n0 + rA + 8;
    int qlo = (nlo < NN) ? nodeBatch[nlo] : 0;
    int qhi = (nhi < NN) ? nodeBatch[nhi] : 0;
    #pragma unroll
    for (int nt = 0; nt < 16; nt++) {
        int c = nt * 8 + tig2;
        if (nt < 8) {
            float bA0 = g_biasAB[c], bA1 = g_biasAB[c + 1];
            if (nlo < NN) {
                g_ABn[(size_t)nlo * 64 + c]     = acc[nt*4+0] + bA0 + g_Aq[qlo * 64 + c];
                g_ABn[(size_t)nlo * 64 + c + 1] = acc[nt*4+1] + bA1 + g_Aq[qlo * 64 + c + 1];
            }
            if (nhi < NN) {
                g_ABn[(size_t)nhi * 64 + c]     = acc[nt*4+2] + bA0 + g_Aq[qhi * 64 + c];
                g_ABn[(size_t)nhi * 64 + c + 1] = acc[nt*4+3] + bA1 + g_Aq[qhi * 64 + c + 1];
            }
        } else {
            int cc = c - 64;
            float bC0 = g_biasC[cc], bC1 = g_biasC[cc + 1];
            if (nlo < NN) {
                g_Cn[(size_t)nlo * 64 + cc]     = acc[nt*4+0] + bC0;
                g_Cn[(size_t)nlo * 64 + cc + 1] = acc[nt*4+1] + bC1;
            }
            if (nhi < NN) {
                g_Cn[(size_t)nhi * 64 + cc]     = acc[nt*4+2] + bC0;
                g_Cn[(size_t)nhi * 64 + cc + 1] = acc[nt*4+3] + bC1;
            }
        }
    }
}

// ---------------- persistent edge kernel: fp16 mma, 128 edges/tile (round-5 config) ----------------
// smem (half2 units): sEE[128*40]=5120 | sMt[64*40]=2560 | sW2t[128*40]=5120
// then floats: sWh[128] | sb2[128] | int sHT[256]
#define H2_EE 0
#define H2_M  5120
#define H2_W2 7680
#define H2_END 12800
#define SME_BYTES (H2_END * 4 + (256 + 256) * 4)

__global__ __launch_bounds__(256, 2) void edge_kernel(const float* __restrict__ edgeEmb,
                                                      const int*   __restrict__ edgeIndex,
                                                      const float* __restrict__ b2,
                                                      const float* __restrict__ Wh,
                                                      const float* __restrict__ bh,
                                                      float* __restrict__ out) {
    extern __shared__ __half2 smh[];
    __half2* sEE  = smh + H2_EE;
    __half2* sMt  = smh + H2_M;
    __half2* sW2t = smh + H2_W2;
    float*   fend = (float*)(smh + H2_END);
    float*   sWh  = fend;
    float*   sb2  = fend + 128;
    int*     sHT  = (int*)(fend + 256);

    int t = threadIdx.x;

    // ---- load weights ONCE ----
    for (int i = t; i < 2048; i += 256) sMt [(i >> 5) * 40 + (i & 31)] = g_Mt[i];
    for (int i = t; i < 4096; i += 256) sW2t[(i >> 5) * 40 + (i & 31)] = g_W2t[i];
    if (t < 128) { sWh[t] = Wh[t]; sb2[t] = b2[t]; }
    float bhv = bh[0];

    int w = t >> 5, lane = t & 31;
    int g = lane >> 2, tig = lane & 3;
    int rA = w * 16 + g;
    int tig2 = tig << 1;

    // fill positions for this thread's 8 float4 chunks
    int fpos1[8], fpos2[8], frow[8];
    #pragma unroll
    for (int j = 0; j < 8; j++) {
        int i = t + 256 * j;
        frow[j]  = i >> 4;
        int q    = i & 15;
        fpos1[j] = permp(2 * q);
        fpos2[j] = permp(2 * q + 1);
    }

    // ---- prefetch first tile ----
    float4 pv[8];
    int ih = 0, itl = 0;
    int tile = blockIdx.x;
    if (tile < NTILES) {
        int e0 = tile * 128;
        #pragma unroll
        for (int j = 0; j < 8; j++) {
            int i = t + 256 * j;
            pv[j] = ((const float4*)edgeEmb)[(size_t)(e0 + (i >> 4)) * 16 + (i & 15)];
        }
        if (t < 128) { ih = edgeIndex[e0 + t]; itl = edgeIndex[NE + e0 + t]; }
    }

    for (; tile < NTILES; tile += gridDim.x) {
        int e0 = tile * 128;
        __syncthreads();                 // prior tile's smem reads done
        #pragma unroll
        for (int j = 0; j < 8; j++) {
            __half2* row = &sEE[frow[j] * 40];
            row[fpos1[j]] = __floats2half2_rn(pv[j].x, pv[j].y);
            row[fpos2[j]] = __floats2half2_rn(pv[j].z, pv[j].w);
        }
        if (t < 128) { sHT[t] = ih; sHT[128 + t] = itl; }
        __syncthreads();                 // tile visible

        // ---- prefetch next tile (hidden under mma work) ----
        int nxt = tile + gridDim.x;
        if (nxt < NTILES) {
            int e0n = nxt * 128;
            #pragma unroll
            for (int j = 0; j < 8; j++) {
                int i = t + 256 * j;
                pv[j] = ((const float4*)edgeEmb)[(size_t)(e0n + (i >> 4)) * 16 + (i & 15)];
            }
            if (t < 128) { ih = edgeIndex[e0n + t]; itl = edgeIndex[NE + e0n + t]; }
        }

        // ---- gather G = ABn[head] + Cn[tail] directly into accumulators (L2) ----
        int h0 = sHT[rA],     t0 = sHT[128 + rA];
        int h1 = sHT[rA + 8], t1 = sHT[128 + rA + 8];
        const float2* A0 = (const float2*)(g_ABn + (size_t)h0 * EMB);
        const float2* C0 = (const float2*)(g_Cn  + (size_t)t0 * EMB);
        const float2* A1 = (const float2*)(g_ABn + (size_t)h1 * EMB);
        const float2* C1 = (const float2*)(g_Cn  + (size_t)t1 * EMB);

        float acc[32];
        #pragma unroll
        for (int nt = 0; nt < 8; nt++) {
            float2 a = A0[nt * 4 + tig], c = C0[nt * 4 + tig];
            float2 b = A1[nt * 4 + tig], d = C1[nt * 4 + tig];
            acc[nt*4+0] = a.x + c.x; acc[nt*4+1] = a.y + c.y;
            acc[nt*4+2] = b.x + d.x; acc[nt*4+3] = b.y + d.y;
        }

        // ---- stage 1: H = relu(EE @ M + G), fp16 m16n8k16 ----
        const __half2* eeLo = &sEE[rA * 40 + tig2];
        const __half2* eeHi = &sEE[(rA + 8) * 40 + tig2];
        #pragma unroll
        for (int kt = 0; kt < 4; kt++) {
            int base = kt * 8;
            uint2 va = *(const uint2*)(eeLo + base);
            uint2 vb = *(const uint2*)(eeHi + base);
            #pragma unroll
            for (int nt = 0; nt < 8; nt++) {
                uint2 wb = *(const uint2*)(&sMt[(nt * 8 + g) * 40 + base + tig2]);
                mma_f16(acc[nt*4], acc[nt*4+1], acc[nt*4+2], acc[nt*4+3],
                        va.x, vb.x, va.y, vb.y, wb.x, wb.y);
            }
        }
        __syncwarp();                    // warp done reading its EE rows
        #pragma unroll
        for (int nt = 0; nt < 8; nt++) {
            int pos = permp(nt * 4 + tig);
            sEE[rA * 40 + pos]       = __floats2half2_rn(fmaxf(acc[nt*4+0], 0.f),
                                                         fmaxf(acc[nt*4+1], 0.f));
            sEE[(rA + 8) * 40 + pos] = __floats2half2_rn(fmaxf(acc[nt*4+2], 0.f),
                                                         fmaxf(acc[nt*4+3], 0.f));
        }
        __syncwarp();                    // H visible to whole warp

        // ---- stage 2: z = relu(H @ W2 + b2); logit = z.Wh (two 64-col halves) ----
        float p0 = 0.f, p1 = 0.f;
        #pragma unroll
        for (int half = 0; half < 2; half++) {
            int cbase = half * 64;
            float acc2[32];
            #pragma unroll
            for (int nt = 0; nt < 8; nt++) {
                float bz0 = sb2[cbase + nt * 8 + tig2];
                float bz1 = sb2[cbase + nt * 8 + tig2 + 1];
                acc2[nt*4+0] = bz0; acc2[nt*4+1] = bz1;
                acc2[nt*4+2] = bz0; acc2[nt*4+3] = bz1;
            }
            #pragma unroll
            for (int kt = 0; kt < 4; kt++) {
                int base = kt * 8;
                uint2 va = *(const uint2*)(eeLo + base);
                uint2 vb = *(const uint2*)(eeHi + base);
                #pragma unroll
                for (int nt = 0; nt < 8; nt++) {
                    uint2 wb = *(const uint2*)(&sW2t[(cbase + nt * 8 + g) * 40 + base + tig2]);
                    mma_f16(acc2[nt*4], acc2[nt*4+1], acc2[nt*4+2], acc2[nt*4+3],
                            va.x, vb.x, va.y, vb.y, wb.x, wb.y);
                }
            }
            #pragma unroll
            for (int nt = 0; nt < 8; nt++) {
                float w0 = sWh[cbase + nt * 8 + tig2];
                float w1 = sWh[cbase + nt * 8 + tig2 + 1];
                p0 += fmaxf(acc2[nt*4+0], 0.f) * w0 + fmaxf(acc2[nt*4+1], 0.f) * w1;
                p1 += fmaxf(acc2[nt*4+2], 0.f) * w0 + fmaxf(acc2[nt*4+3], 0.f) * w1;
            }
        }
        p0 += __shfl_xor_sync(0xffffffffu, p0, 1);
        p0 += __shfl_xor_sync(0xffffffffu, p0, 2);
        p1 += __shfl_xor_sync(0xffffffffu, p1, 1);
        p1 += __shfl_xor_sync(0xffffffffu, p1, 2);
        if (tig == 0) {
            out[e0 + rA]     = 1.f / (1.f + __expf(-(p0 + bhv)));
            out[e0 + rA + 8] = 1.f / (1.f + __expf(-(p1 + bhv)));
        }
    }
}

// ---------------- launch ----------------
extern "C" void kernel_launch(void* const* d_in, const int* in_sizes, int n_in,
                              void* d_out, int out_size) {
    const float* question_emb = (const float*)d_in[0];
    const float* node_emb     = (const float*)d_in[1];
    const float* edge_emb     = (const float*)d_in[2];
    const int*   edge_index   = (const int*)  d_in[3];
    const int*   node_batch   = (const int*)  d_in[4];
    const float* Wq = (const float*)d_in[5];
    const float* bq = (const float*)d_in[6];
    const float* We = (const float*)d_in[7];
    const float* be = (const float*)d_in[8];
    const float* Wr = (const float*)d_in[9];
    const float* br = (const float*)d_in[10];
    const float* W1 = (const float*)d_in[11];
    const float* b1 = (const float*)d_in[12];
    const float* W2 = (const float*)d_in[13];
    const float* b2 = (const float*)d_in[14];
    const float* Wh = (const float*)d_in[15];
    const float* bh = (const float*)d_in[16];
    float* out = (float*)d_out;

    prep0_kernel<<<16, 256>>>(question_emb, Wq, bq);
    prep1_kernel<<<65, 256>>>(We, be, Wr, br, W1, b1);
    prep2_kernel<<<40, 256>>>(W2);
    node_mma_kernel<<<(NN + 127) / 128, 256>>>(node_emb, node_batch);

    cudaFuncSetAttribute(edge_kernel, cudaFuncAttributeMaxDynamicSharedMemorySize, SME_BYTES);
    edge_kernel<<<296, 256, SME_BYTES>>>(edge_emb, edge_index, b2, Wh, bh, out);
}